// round 2
// baseline (speedup 1.0000x reference)
#include <cuda_runtime.h>
#include <cstdint>

#define BATCH   512
#define MEM     256
#define FEAT    512
#define NCOL    131072      // 64*2048
#define TOPK    16
#define CHUNK   128         // columns cached per block in gather kernel
#define K2_THREADS 512
#define K2_SMEM (MEM*CHUNK*4 + BATCH*TOPK*8)   // 131072 + 65536 = 196608 B

// Scratch: per (batch, k) -> (weight bits, memory row index)
__device__ uint2 g_pairs[BATCH * TOPK];

// ---------------------------------------------------------------------------
// Kernel 1: cosine similarity, top-16, clamp>=0, renormalize.
// One block per batch sample, 256 threads (one per memory row).
// ---------------------------------------------------------------------------
__global__ void topk_kernel(const float* __restrict__ features,
                            const float* __restrict__ keys) {
    __shared__ float f_s[FEAT];
    __shared__ float sim_s[MEM];
    __shared__ float red_v[MEM];
    __shared__ int   red_i[MEM];
    __shared__ float top_v[TOPK];
    __shared__ int   top_i[TOPK];
    __shared__ float fnorm_s;

    const int b = blockIdx.x;
    const int t = threadIdx.x;

    // stage feature row
    f_s[t]       = features[b * FEAT + t];
    f_s[t + 256] = features[b * FEAT + t + 256];
    __syncthreads();

    // ||f|| via block reduce
    red_v[t] = f_s[t] * f_s[t] + f_s[t + 256] * f_s[t + 256];
    __syncthreads();
    for (int s = 128; s > 0; s >>= 1) {
        if (t < s) red_v[t] += red_v[t + s];
        __syncthreads();
    }
    if (t == 0) fnorm_s = fmaxf(sqrtf(red_v[0]), 1e-8f);
    __syncthreads();
    const float fn = fnorm_s;

    // thread t owns memory row t: dot(f, key_t) and ||key_t||
    const float4* krow = reinterpret_cast<const float4*>(keys + t * FEAT);
    const float4* f4   = reinterpret_cast<const float4*>(f_s);
    float dot = 0.f, kn = 0.f;
#pragma unroll 8
    for (int d = 0; d < FEAT / 4; d++) {
        float4 kv = krow[d];
        float4 fv = f4[d];
        dot += kv.x * fv.x + kv.y * fv.y + kv.z * fv.z + kv.w * fv.w;
        kn  += kv.x * kv.x + kv.y * kv.y + kv.z * kv.z + kv.w * kv.w;
    }
    const float nk = fmaxf(sqrtf(kn), 1e-8f);
    sim_s[t] = dot / (fn * nk);
    __syncthreads();

    // 16 sequential argmax reductions (tie -> smaller index, matching
    // first-occurrence top_k semantics)
    for (int k = 0; k < TOPK; k++) {
        red_v[t] = sim_s[t];
        red_i[t] = t;
        __syncthreads();
        for (int s = 128; s > 0; s >>= 1) {
            if (t < s) {
                float v2 = red_v[t + s];
                int   i2 = red_i[t + s];
                if (v2 > red_v[t] || (v2 == red_v[t] && i2 < red_i[t])) {
                    red_v[t] = v2;
                    red_i[t] = i2;
                }
            }
            __syncthreads();
        }
        if (t == 0) {
            top_v[k] = red_v[0];
            top_i[k] = red_i[0];
            sim_s[red_i[0]] = -3.0e38f;   // remove from candidates
        }
        __syncthreads();
    }

    // clamp negatives, normalize, emit (w, idx) pairs
    if (t == 0) {
        float s = 0.f;
#pragma unroll
        for (int k = 0; k < TOPK; k++) {
            float v = fmaxf(top_v[k], 0.f);
            top_v[k] = v;
            s += v;
        }
        const float inv = 1.0f / s;   // s==0 -> inf; 0*inf = NaN matches ref 0/0
#pragma unroll
        for (int k = 0; k < TOPK; k++) {
            uint2 pr;
            pr.x = __float_as_uint(top_v[k] * inv);
            pr.y = (unsigned)top_i[k];
            g_pairs[b * TOPK + k] = pr;
        }
    }
}

// ---------------------------------------------------------------------------
// Kernel 2: ctx = W_sparse @ memory, column-chunked.
// Each block caches memory[:, chunk*128 : chunk*128+128] (all 256 rows) in
// SMEM (128 KB) plus all (w, idx) pairs (64 KB), then streams all 512 batches
// against it. Every memory byte is read from DRAM exactly once.
// ---------------------------------------------------------------------------
__global__ void __launch_bounds__(K2_THREADS, 1)
gather_kernel(const float* __restrict__ memory, float* __restrict__ out) {
    extern __shared__ float smem[];
    float4* mem_s4  = reinterpret_cast<float4*>(smem);                 // [256][32] float4
    uint2*  pairs_s = reinterpret_cast<uint2*>(smem + MEM * CHUNK);    // [512][16]

    const int tid   = threadIdx.x;
    const int chunk = blockIdx.x;

    // fill memory tile: 256 rows x 32 float4 (coalesced per row segment)
    const float4* gmem4 = reinterpret_cast<const float4*>(memory) +
                          (size_t)chunk * (CHUNK / 4);
    for (int i = tid; i < MEM * (CHUNK / 4); i += K2_THREADS) {
        int row = i >> 5;          // CHUNK/4 == 32
        int q   = i & 31;
        mem_s4[i] = gmem4[(size_t)row * (NCOL / 4) + q];
    }
    // fill pairs
    for (int i = tid; i < BATCH * TOPK; i += K2_THREADS)
        pairs_s[i] = g_pairs[i];
    __syncthreads();

    const int warp = tid >> 5;
    const int lane = tid & 31;
    float4* out4 = reinterpret_cast<float4*>(out);

    // 16 warps; warp w handles batches w, w+16, ... (32 batches each).
    // Lane covers 4 consecutive columns via LDS.128 (conflict-free, 4-phase).
    for (int b = warp; b < BATCH; b += 16) {
        const uint4* pb = reinterpret_cast<const uint4*>(&pairs_s[b * TOPK]);
        float4 acc = make_float4(0.f, 0.f, 0.f, 0.f);
#pragma unroll
        for (int j = 0; j < TOPK / 2; j++) {
            uint4 pr2 = pb[j];                     // (w0,i0,w1,i1), broadcast
            float w0 = __uint_as_float(pr2.x);
            float w1 = __uint_as_float(pr2.z);
            float4 v0 = mem_s4[pr2.y * 32 + lane];
            float4 v1 = mem_s4[pr2.w * 32 + lane];
            acc.x += w0 * v0.x; acc.y += w0 * v0.y;
            acc.z += w0 * v0.z; acc.w += w0 * v0.w;
            acc.x += w1 * v1.x; acc.y += w1 * v1.y;
            acc.z += w1 * v1.z; acc.w += w1 * v1.w;
        }
        out4[(size_t)b * (NCOL / 4) + (size_t)chunk * 32 + lane] = acc;
    }
}

// ---------------------------------------------------------------------------
extern "C" void kernel_launch(void* const* d_in, const int* in_sizes, int n_in,
                              void* d_out, int out_size) {
    const float* features = (const float*)d_in[0];
    const float* keys     = (const float*)d_in[1];
    const float* memory   = (const float*)d_in[2];
    float*       out      = (float*)d_out;

    cudaFuncSetAttribute(gather_kernel,
                         cudaFuncAttributeMaxDynamicSharedMemorySize, K2_SMEM);

    topk_kernel<<<BATCH, 256>>>(features, keys);
    gather_kernel<<<NCOL / CHUNK, K2_THREADS, K2_SMEM>>>(memory, out);
}

// round 3
// speedup vs baseline: 1.7772x; 1.7772x over previous
#include <cuda_runtime.h>
#include <cuda_fp16.h>
#include <cstdint>

#define BATCH   512
#define MEM     256
#define FEAT    512
#define NCOL    131072      // 64*2048
#define TOPK    16

#define CHUNK   256         // columns cached per block (fp16) in gather kernel
#define GT      1024        // gather threads
#define TILE_BYTES (MEM*CHUNK*2)            // 131072
#define K2_SMEM   (TILE_BYTES + BATCH*TOPK*8)  // 131072 + 65536 = 196608

// Scratch: per (batch, k) -> (weight bits, memory row index)
__device__ uint2 g_pairs[BATCH * TOPK];

// ---------------------------------------------------------------------------
// Kernel 1: cosine similarity + top-16 + clamp + renormalize.
// 128 blocks x 256 threads; each block handles 4 batches.
// Dot phase: thread t owns key row t; features broadcast from SMEM.
// Topk phase: warp w (w<4) does batch w's top-16 with register-resident sims.
// ---------------------------------------------------------------------------
__global__ void __launch_bounds__(256)
topk_kernel(const float* __restrict__ features, const float* __restrict__ keys) {
    __shared__ float f_s[4 * FEAT];          // 8 KB
    __shared__ float fn_s[4];
    __shared__ float sim_s[4 * 264];         // padded rows
    __shared__ float topv_s[4][TOPK];
    __shared__ int   topi_s[4][TOPK];

    const int t    = threadIdx.x;
    const int warp = t >> 5;
    const int lane = t & 31;
    const int base = blockIdx.x * 4;

    // stage 4 feature rows
    float4* f4s = reinterpret_cast<float4*>(f_s);
    const float4* fg = reinterpret_cast<const float4*>(features) + (size_t)base * (FEAT / 4);
    for (int i = t; i < 4 * FEAT / 4; i += 256) f4s[i] = fg[i];
    __syncthreads();

    // feature norms: warp w computes ||f_w||
    if (warp < 4) {
        float s = 0.f;
#pragma unroll
        for (int m = 0; m < FEAT / 32; m++) {
            float v = f_s[warp * FEAT + lane + m * 32];
            s += v * v;
        }
#pragma unroll
        for (int off = 16; off; off >>= 1) s += __shfl_down_sync(0xffffffffu, s, off);
        if (lane == 0) fn_s[warp] = fmaxf(sqrtf(s), 1e-8f);
    }
    __syncthreads();

    // dots: thread t owns key row t (t in [0,256))
    const float4* krow = reinterpret_cast<const float4*>(keys) + (size_t)t * (FEAT / 4);
    float acc[4] = {0.f, 0.f, 0.f, 0.f};
    float kn = 0.f;
#pragma unroll 4
    for (int d = 0; d < FEAT / 4; d++) {
        float4 kv = krow[d];
        kn += kv.x * kv.x + kv.y * kv.y + kv.z * kv.z + kv.w * kv.w;
#pragma unroll
        for (int b = 0; b < 4; b++) {
            float4 fv = f4s[b * (FEAT / 4) + d];   // broadcast
            acc[b] += kv.x * fv.x + kv.y * fv.y + kv.z * fv.z + kv.w * fv.w;
        }
    }
    const float rkn = fmaxf(sqrtf(kn), 1e-8f);
#pragma unroll
    for (int b = 0; b < 4; b++)
        sim_s[b * 264 + t] = acc[b] / (fn_s[b] * rkn);
    __syncthreads();

    // per-warp top-16: warp w handles batch w
    if (warp < 4) {
        float v[8];
#pragma unroll
        for (int m = 0; m < 8; m++) v[m] = sim_s[warp * 264 + lane * 8 + m];

        for (int k = 0; k < TOPK; k++) {
            // local argmax over 8 register values (ties -> smaller m)
            float best = v[0];
            int bm = 0;
#pragma unroll
            for (int m = 1; m < 8; m++)
                if (v[m] > best) { best = v[m]; bm = m; }
            int gi = lane * 8 + bm;
            // warp argmax (ties -> smaller global index)
#pragma unroll
            for (int off = 16; off; off >>= 1) {
                float ov = __shfl_down_sync(0xffffffffu, best, off);
                int   oi = __shfl_down_sync(0xffffffffu, gi,   off);
                if (ov > best || (ov == best && oi < gi)) { best = ov; gi = oi; }
            }
            best = __shfl_sync(0xffffffffu, best, 0);
            gi   = __shfl_sync(0xffffffffu, gi,   0);
            // knock out the winner
            if (lane == (gi >> 3)) {
                int li = gi & 7;
#pragma unroll
                for (int m = 0; m < 8; m++)
                    if (m == li) v[m] = -3.0e38f;
            }
            if (lane == 0) { topv_s[warp][k] = best; topi_s[warp][k] = gi; }
        }
        __syncwarp();

        // clamp + normalize + emit pairs
        float tv = (lane < TOPK) ? fmaxf(topv_s[warp][lane], 0.f) : 0.f;
        float s = tv;
#pragma unroll
        for (int off = 16; off; off >>= 1) s += __shfl_down_sync(0xffffffffu, s, off);
        s = __shfl_sync(0xffffffffu, s, 0);
        const float inv = 1.0f / s;   // s==0 -> inf; 0*inf=NaN matches ref 0/0
        if (lane < TOPK) {
            uint2 pr;
            pr.x = __float_as_uint(tv * inv);
            pr.y = (unsigned)topi_s[warp][lane];
            g_pairs[(base + warp) * TOPK + lane] = pr;
        }
    }
}

// ---------------------------------------------------------------------------
// Kernel 2: ctx = W_sparse @ memory, column-chunked, fp16 SMEM tile.
// Each block caches memory[:, c*256 : c*256+256] for all 256 rows as fp16
// (128 KB) + all (w, idx) pairs (64 KB). All 512 batches stream against it.
// Each memory byte is read from DRAM exactly once; accumulation is fp32.
// ---------------------------------------------------------------------------
__device__ __forceinline__ void fma8(float acc[8], uint4 d, float w) {
    float2 f0 = __half22float2(*reinterpret_cast<__half2*>(&d.x));
    float2 f1 = __half22float2(*reinterpret_cast<__half2*>(&d.y));
    float2 f2 = __half22float2(*reinterpret_cast<__half2*>(&d.z));
    float2 f3 = __half22float2(*reinterpret_cast<__half2*>(&d.w));
    acc[0] += w * f0.x; acc[1] += w * f0.y;
    acc[2] += w * f1.x; acc[3] += w * f1.y;
    acc[4] += w * f2.x; acc[5] += w * f2.y;
    acc[6] += w * f3.x; acc[7] += w * f3.y;
}

__global__ void __launch_bounds__(GT, 1)
gather_kernel(const float* __restrict__ memory, float* __restrict__ out) {
    extern __shared__ char smem[];
    uint2* tile2   = reinterpret_cast<uint2*>(smem);                 // half2x2, 8B = 4 cols
    const uint4* tile4 = reinterpret_cast<const uint4*>(smem);       // 16B = 8 cols
    uint2* pairs_s = reinterpret_cast<uint2*>(smem + TILE_BYTES);    // [512][16]

    const int tid   = threadIdx.x;
    const int chunk = blockIdx.x;

    // fill fp16 tile: 256 rows x 64 float4 each (coalesced), convert to half2
    const float4* gmem4 = reinterpret_cast<const float4*>(memory) +
                          (size_t)chunk * (CHUNK / 4);
    for (int i = tid; i < MEM * (CHUNK / 4); i += GT) {
        int row = i >> 6;          // CHUNK/4 == 64
        int c4  = i & 63;
        float4 v = gmem4[(size_t)row * (NCOL / 4) + c4];
        __half2 h0 = __floats2half2_rn(v.x, v.y);
        __half2 h1 = __floats2half2_rn(v.z, v.w);
        uint2 pk;
        pk.x = *reinterpret_cast<uint32_t*>(&h0);
        pk.y = *reinterpret_cast<uint32_t*>(&h1);
        tile2[row * 64 + c4] = pk;
    }
    // fill pairs
    for (int i = tid; i < BATCH * TOPK; i += GT)
        pairs_s[i] = g_pairs[i];
    __syncthreads();

    const int warp = tid >> 5;   // 32 warps
    const int lane = tid & 31;
    float4* out4 = reinterpret_cast<float4*>(out);

    // warp w handles batches w, w+32, ... (16 each). Lane covers 8 cols
    // via one LDS.128 of the fp16 tile (conflict-free, 4-phase).
    for (int b = warp; b < BATCH; b += 32) {
        const uint4* pb = reinterpret_cast<const uint4*>(&pairs_s[b * TOPK]);
        float acc[8] = {0.f, 0.f, 0.f, 0.f, 0.f, 0.f, 0.f, 0.f};
#pragma unroll 4
        for (int j = 0; j < TOPK / 2; j++) {
            uint4 pr = pb[j];                      // (w0,i0,w1,i1), broadcast
            float w0 = __uint_as_float(pr.x);
            float w1 = __uint_as_float(pr.z);
            uint4 d0 = tile4[pr.y * 32 + lane];
            uint4 d1 = tile4[pr.w * 32 + lane];
            fma8(acc, d0, w0);
            fma8(acc, d1, w1);
        }
        float4 o0 = make_float4(acc[0], acc[1], acc[2], acc[3]);
        float4 o1 = make_float4(acc[4], acc[5], acc[6], acc[7]);
        size_t obase = (size_t)b * (NCOL / 4) + (size_t)chunk * (CHUNK / 4) + lane * 2;
        out4[obase]     = o0;
        out4[obase + 1] = o1;
    }
}

// ---------------------------------------------------------------------------
extern "C" void kernel_launch(void* const* d_in, const int* in_sizes, int n_in,
                              void* d_out, int out_size) {
    const float* features = (const float*)d_in[0];
    const float* keys     = (const float*)d_in[1];
    const float* memory   = (const float*)d_in[2];
    float*       out      = (float*)d_out;

    cudaFuncSetAttribute(gather_kernel,
                         cudaFuncAttributeMaxDynamicSharedMemorySize, K2_SMEM);

    topk_kernel<<<BATCH / 4, 256>>>(features, keys);
    gather_kernel<<<NCOL / CHUNK, GT, K2_SMEM>>>(memory, out);
}